// round 7
// baseline (speedup 1.0000x reference)
#include <cuda_runtime.h>
#include <math.h>
#include <stdint.h>

#define NMAX   100000
#define EMAX   600000
#define HIDDIM 128

// Scratch (device globals)
__device__ float g_deg[NMAX];
__device__ float g_dinv[NMAX];
__device__ int   g_head[NMAX];
__device__ int   g_next[EMAX];
__device__ float g_h  [(size_t)NMAX * HIDDIM];
__device__ float g_agg[(size_t)NMAX * HIDDIM];
__device__ float g_pooled[HIDDIM];

__device__ __forceinline__ float elu1(float x) { return x > 0.0f ? x : expm1f(x); }
__device__ __forceinline__ float tf32rna(float x) {
    float r; asm("cvt.rna.tf32.f32 %0, %1;" : "=f"(r) : "f"(x)); return r;
}

// ---------------------------------------------------------------------------
__global__ void k_init(int N)
{
    int i = blockIdx.x * blockDim.x + threadIdx.x;
    if (i < N) { g_deg[i] = 1.0f; g_head[i] = -1; }
    if (blockIdx.x == 0 && threadIdx.x < HIDDIM) g_pooled[threadIdx.x] = 0.0f;
}

__global__ void k_lbuild(const int* __restrict__ col, int E, int N)
{
    int e = blockIdx.x * blockDim.x + threadIdx.x;
    if (e < E) {
        unsigned c = (unsigned)col[e];
        if (c < (unsigned)N) {
            g_next[e] = atomicExch(&g_head[c], e);
            atomicAdd(&g_deg[c], 1.0f);
        }
    }
}

__global__ void k_dinv(int N)
{
    int i = blockIdx.x * blockDim.x + threadIdx.x;
    if (i < N) g_dinv[i] = rsqrtf(g_deg[i]);
}

// ---------------------------------------------------------------------------
// Tensor-core GEMM via legacy mma.sync (baseline PTX — compute_103-safe):
//   H = ACT(Xsrc) @ (W_hi + W_lo),  tile 128x128, K chunked by 32.
// A = tf32(x) (rna), B = W^T split into tf32 hi+lo (compensated).
// Smem XOR-swizzle: physical col = col ^ ((row & 7) << 2)  -> conflict-free
// fragment loads for both A (m-major) and B (n-major) tiles.

__device__ __forceinline__ void mma_tf32(float* d, const uint32_t* a,
                                         uint32_t b0, uint32_t b1)
{
    asm volatile(
        "mma.sync.aligned.m16n8k8.row.col.f32.tf32.tf32.f32 "
        "{%0,%1,%2,%3}, {%4,%5,%6,%7}, {%8,%9}, {%0,%1,%2,%3};"
        : "+f"(d[0]), "+f"(d[1]), "+f"(d[2]), "+f"(d[3])
        : "r"(a[0]), "r"(a[1]), "r"(a[2]), "r"(a[3]), "r"(b0), "r"(b1));
}

__global__ __launch_bounds__(256) void k_gemm_mma(const float* __restrict__ Xin,
                                                  int layer,
                                                  const float* __restrict__ bprev,
                                                  const float* __restrict__ W,
                                                  int N)
{
    __shared__ float Xs[128 * 32];   // 16 KB  (A chunk, m-major, swizzled)
    __shared__ float Bh[128 * 32];   // 16 KB  (W^T hi, n-major, swizzled)
    __shared__ float Bl[128 * 32];   // 16 KB  (W^T lo)

    const int t    = threadIdx.x;
    const int lane = t & 31;
    const int wid  = t >> 5;
    const int warp_m = (wid & 3) * 32;   // 4 warps down  -> 32 rows each
    const int warp_n = (wid >> 2) * 64;  // 2 warps across-> 64 cols each
    const int node0 = blockIdx.x * 128;

    float acc[2][8][4];
#pragma unroll
    for (int i = 0; i < 2; i++)
#pragma unroll
        for (int j = 0; j < 8; j++)
#pragma unroll
            for (int q = 0; q < 4; q++) acc[i][j][q] = 0.0f;

    for (int kc = 0; kc < 4; kc++) {
        const int k0g = kc * 32;

        // ---- stage X chunk: 128 rows x 8 float4 (fused ELU for layer>0) ----
        for (int idx = t; idx < 128 * 8; idx += 256) {
            int m = idx >> 3, k4 = idx & 7;
            int gn = node0 + m;
            float4 v = make_float4(0.f, 0.f, 0.f, 0.f);
            if (gn < N) {
                if (layer == 0) {
                    v = *(const float4*)(Xin + (size_t)gn * 128 + k0g + k4 * 4);
                } else {
                    float4 a = *(const float4*)(g_agg + (size_t)gn * 128 + k0g + k4 * 4);
                    float4 bb = *(const float4*)(bprev + k0g + k4 * 4);
                    v.x = elu1(a.x + bb.x); v.y = elu1(a.y + bb.y);
                    v.z = elu1(a.z + bb.z); v.w = elu1(a.w + bb.w);
                }
                v.x = tf32rna(v.x); v.y = tf32rna(v.y);
                v.z = tf32rna(v.z); v.w = tf32rna(v.w);
            }
            int pc = (k4 * 4) ^ ((m & 7) << 2);
            *(float4*)&Xs[m * 32 + pc] = v;
        }

        // ---- stage W chunk transposed + hi/lo split: 32 k x 128 n ----
        for (int idx = t; idx < 32 * 32; idx += 256) {
            int k = idx >> 5, n4 = idx & 31;
            float4 w = *(const float4*)(W + (size_t)(k0g + k) * 128 + n4 * 4);
            float wv[4] = {w.x, w.y, w.z, w.w};
#pragma unroll
            for (int j = 0; j < 4; j++) {
                int n = n4 * 4 + j;
                float hi = tf32rna(wv[j]);
                float lo = tf32rna(wv[j] - hi);
                int pc = k ^ ((n & 7) << 2);
                Bh[n * 32 + pc] = hi;
                Bl[n * 32 + pc] = lo;
            }
        }
        __syncthreads();

        // ---- compute: 4 k-steps of 8 ----
#pragma unroll
        for (int ks = 0; ks < 4; ks++) {
            const int kb = ks * 8;
            uint32_t a[2][4];
#pragma unroll
            for (int ma = 0; ma < 2; ma++) {
                int m = warp_m + ma * 16 + (lane >> 2);
                int kk = kb + (lane & 3);
                int perm = (m & 7) << 2;       // same for m and m+8
                a[ma][0] = __float_as_uint(Xs[m * 32 + (kk ^ perm)]);
                a[ma][1] = __float_as_uint(Xs[(m + 8) * 32 + (kk ^ perm)]);
                a[ma][2] = __float_as_uint(Xs[m * 32 + ((kk + 4) ^ perm)]);
                a[ma][3] = __float_as_uint(Xs[(m + 8) * 32 + ((kk + 4) ^ perm)]);
            }
#pragma unroll
            for (int na = 0; na < 8; na++) {
                int n = warp_n + na * 8 + (lane >> 2);
                int kk = kb + (lane & 3);
                int perm = (n & 7) << 2;
                uint32_t bh0 = __float_as_uint(Bh[n * 32 + (kk ^ perm)]);
                uint32_t bh1 = __float_as_uint(Bh[n * 32 + ((kk + 4) ^ perm)]);
                mma_tf32(acc[0][na], a[0], bh0, bh1);
                mma_tf32(acc[1][na], a[1], bh0, bh1);
                uint32_t bl0 = __float_as_uint(Bl[n * 32 + (kk ^ perm)]);
                uint32_t bl1 = __float_as_uint(Bl[n * 32 + ((kk + 4) ^ perm)]);
                mma_tf32(acc[0][na], a[0], bl0, bl1);
                mma_tf32(acc[1][na], a[1], bl0, bl1);
            }
        }
        __syncthreads();
    }

    // ---- epilogue: C fragments -> g_h (coalesced 8B stores) ----
#pragma unroll
    for (int ma = 0; ma < 2; ma++) {
        int m  = node0 + warp_m + ma * 16 + (lane >> 2);
        int m8 = m + 8;
#pragma unroll
        for (int na = 0; na < 8; na++) {
            int n = warp_n + na * 8 + 2 * (lane & 3);
            if (m < N)
                *(float2*)(g_h + (size_t)m * 128 + n) =
                    make_float2(acc[ma][na][0], acc[ma][na][1]);
            if (m8 < N)
                *(float2*)(g_h + (size_t)m8 * 128 + n) =
                    make_float2(acc[ma][na][2], acc[ma][na][3]);
        }
    }
}

// ---------------------------------------------------------------------------
// gather aggregation (no atomics): one warp per node v
__global__ void k_gather(const int* __restrict__ row, int N)
{
    int v = (blockIdx.x * blockDim.x + threadIdx.x) >> 5;
    int lane = threadIdx.x & 31;
    if (v >= N) return;

    float dv = g_dinv[v];
    float4 acc = ((const float4*)(g_h + (size_t)v * 128))[lane];
    float d2 = dv * dv;
    acc.x *= d2; acc.y *= d2; acc.z *= d2; acc.w *= d2;

    int e = g_head[v];
    while (e >= 0) {
        unsigned u = (unsigned)row[e];
        if (u < (unsigned)N) {
            float coef = g_dinv[u] * dv;
            float4 hv = ((const float4*)(g_h + (size_t)u * 128))[lane];
            acc.x = fmaf(hv.x, coef, acc.x);
            acc.y = fmaf(hv.y, coef, acc.y);
            acc.z = fmaf(hv.z, coef, acc.z);
            acc.w = fmaf(hv.w, coef, acc.w);
        }
        e = g_next[e];
    }
    ((float4*)(g_agg + (size_t)v * 128))[lane] = acc;
}

// ---------------------------------------------------------------------------
__global__ void k_pool(const float* __restrict__ b2, int N)
{
    int j = threadIdx.x;   // 128 threads
    float bj = b2[j];
    float s = 0.0f;
    for (int n = blockIdx.x; n < N; n += gridDim.x)
        s += elu1(g_agg[(size_t)n * 128 + j] + bj);
    atomicAdd(&g_pooled[j], s);
}

__global__ void k_final(const float* __restrict__ lin_w,
                        const float* __restrict__ lin_b,
                        float* __restrict__ out, int N)
{
    int j = threadIdx.x;
    if (j < 24) {
        float invn = 1.0f / (float)N;
        float s = lin_b[j];
#pragma unroll 8
        for (int k = 0; k < 128; k++)
            s += g_pooled[k] * invn * lin_w[k * 24 + j];
        out[j] = s;
    }
}

// ---------------------------------------------------------------------------
extern "C" void kernel_launch(void* const* d_in, const int* in_sizes, int n_in,
                              void* d_out, int out_size)
{
    // ---- Input identification: exact sizes (unit-agnostic), ignore extras.
    int unit = 1;
    {
        bool has24 = false, has96 = false;
        for (int i = 0; i < n_in; i++) {
            if (in_sizes[i] == 24) has24 = true;
            if (in_sizes[i] == 96) has96 = true;
        }
        if (!has24 && has96) unit = 4;
    }

    const float* x = nullptr;  const int* eidx = nullptr;
    const float* Ws[3] = {nullptr,nullptr,nullptr};
    const float* bs[3] = {nullptr,nullptr,nullptr};
    const float* lin_w = nullptr; const float* lin_b = nullptr;
    int iW = 0, ib = 0;

    for (int i = 0; i < n_in; i++) {
        long s = (long)in_sizes[i] / unit;
        if      (s == 12800000 && !x)      x     = (const float*)d_in[i];
        else if (s == 1200000  && !eidx)   eidx  = (const int*)  d_in[i];
        else if (s == 16384 && iW < 3)     Ws[iW++] = (const float*)d_in[i];
        else if (s == 3072  && !lin_w)     lin_w = (const float*)d_in[i];
        else if (s == 128   && ib < 3)     bs[ib++] = (const float*)d_in[i];
        else if (s == 24    && !lin_b)     lin_b = (const float*)d_in[i];
    }
    if (!x || !eidx || iW < 3 || ib < 3 || !lin_w || !lin_b) {
        int order[32];
        int m = (n_in < 32) ? n_in : 32;
        for (int i = 0; i < m; i++) order[i] = i;
        for (int i = 0; i < m; i++) {
            int best = i;
            for (int j = i + 1; j < m; j++)
                if (in_sizes[order[j]] > in_sizes[order[best]]) best = j;
            int tmp = order[best];
            for (int j = best; j > i; j--) order[j] = order[j - 1];
            order[i] = tmp;
        }
        if (m < 10) return;
        x     = (const float*)d_in[order[0]];
        eidx  = (const int*)  d_in[order[1]];
        Ws[0] = (const float*)d_in[order[2]];
        Ws[1] = (const float*)d_in[order[3]];
        Ws[2] = (const float*)d_in[order[4]];
        lin_w = (const float*)d_in[order[5]];
        bs[0] = (const float*)d_in[order[6]];
        bs[1] = (const float*)d_in[order[7]];
        bs[2] = (const float*)d_in[order[8]];
        lin_b = (const float*)d_in[order[9]];
    }
    float* out = (float*)d_out;

    const int N = 100000;
    const int E = 600000;
    const int* e_row = eidx;
    const int* e_col = eidx + E;

    k_init<<<(N + 255) / 256, 256>>>(N);
    k_lbuild<<<(E + 255) / 256, 256>>>(e_col, E, N);
    k_dinv<<<(N + 255) / 256, 256>>>(N);

    const int tc_blocks     = (N + 127) / 128;   // 782
    const int gather_blocks = (N + 7) / 8;

    for (int l = 0; l < 3; l++) {
        k_gemm_mma<<<tc_blocks, 256>>>(x, l, l > 0 ? bs[l - 1] : nullptr,
                                       Ws[l], N);
        k_gather<<<gather_blocks, 256>>>(e_row, N);
    }

    k_pool<<<512, 128>>>(bs[2], N);
    k_final<<<1, 32>>>(lin_w, lin_b, out, N);
}